// round 3
// baseline (speedup 1.0000x reference)
#include <cuda_runtime.h>
#include <cstdint>

// Spatial correlation sampler: out[b, dh*9+dw, h, w] =
//   (1/C) * sum_c in1[b,c,h,w] * in2[b,c,h+dh-4,w+dw-4]   (zero-padded)
// B=8, C=256, H=128, W=256, patch=9.
//
// R3: 8 px/thread, f32x2 px-pairs, conflict-free smem pitches (P2=76, P1=68),
// 3-stage cp.async pipeline (2 ch/stage), hoisted loader, 1 barrier/stage.

#define RAD  4
#define PATCH 9
#define CC_  256
#define HH   128
#define WW   256
#define BB   8

#define TH   8
#define TW   64
#define CCH  2
#define NSTAGE 3
#define ROWS2 (TH + 2*RAD)       // 16
#define P2   76                  // in2 row pitch (floats); 72 used; 19 chunks (odd!)
#define P1   68                  // in1 row pitch (floats); 64 used; 17 chunks (odd!)
#define IN2F (ROWS2 * P2)        // 1216
#define CHF  (IN2F + TH * P1)    // 1760 floats per channel (7040 B, %128==0)
#define STAGEF (CCH * CHF)       // 3520
#define STAGE_B (STAGEF * 4)     // 14080
#define IN2CK (ROWS2 * 18)       // 288 chunks (16B) per channel, in2
#define CHCK  (IN2CK + TH * 16)  // 416 chunks per channel
#define TOTCK (CCH * CHCK)       // 832 chunks per stage
#define NT   576
#define NSTEPS (CC_ / CCH)       // 128 stages

__device__ __forceinline__ unsigned smem_u32(const void* p) {
    return (unsigned)__cvta_generic_to_shared(p);
}
__device__ __forceinline__ void cp16(unsigned dst, const void* src, int src_bytes) {
    asm volatile("cp.async.cg.shared.global [%0], [%1], 16, %2;\n"
                 :: "r"(dst), "l"(src), "r"(src_bytes));
}
__device__ __forceinline__ unsigned long long pk(float lo, float hi) {
    unsigned long long v;
    asm("mov.b64 %0, {%1, %2};" : "=l"(v) : "f"(lo), "f"(hi));
    return v;
}
__device__ __forceinline__ void fma2(unsigned long long& d,
                                     unsigned long long a, unsigned long long b) {
    asm("fma.rn.f32x2 %0, %1, %2, %3;" : "=l"(d) : "l"(a), "l"(b), "l"(d));
}
__device__ __forceinline__ void upk(float& lo, float& hi, unsigned long long v) {
    asm("mov.b64 {%0, %1}, %2;" : "=f"(lo), "=f"(hi) : "l"(v));
}

__global__ void __launch_bounds__(NT, 1)
corr_kernel(const float* __restrict__ in1,
            const float* __restrict__ in2,
            float* __restrict__ out)
{
    __shared__ __align__(16) float sm[NSTAGE * STAGEF];   // 42240 B

    const int tid  = threadIdx.x;
    const int lane = tid & 31;
    const int wg   = lane & 3;         // low 2 bits of w-group
    const int hh   = lane >> 2;        // 0..7 rows
    const int warp = tid >> 5;         // 0..17
    const int wgf  = ((warp & 1) << 2) | wg;   // full w-group 0..7 (8 px each)
    const int dh   = warp >> 1;        // 0..8

    const int w0 = blockIdx.x * TW;
    const int h0 = blockIdx.y * TH;
    const int b  = blockIdx.z;

    const float* __restrict__ in1b = in1 + (size_t)b * CC_ * HH * WW;
    const float* __restrict__ in2b = in2 + (size_t)b * CC_ * HH * WW;

    // ---- hoisted loader slots (stage-invariant except pointer advance) ----
    const unsigned smbase = smem_u32(sm);
    const unsigned smend  = smbase + NSTAGE * STAGE_B;

    const float* src0; unsigned dst0; int sz0;
    const float* src1 = in2b; unsigned dst1 = smbase; int sz1 = 0;
    const bool has1 = (tid < TOTCK - NT);   // tid < 256 gets a 2nd chunk

    auto decode = [&](int i, const float*& src, unsigned& dst, int& sz) {
        int ch = i / CHCK;                 // channel within stage (0..1)
        int r  = i - ch * CHCK;
        sz = 16;
        if (r < IN2CK) {
            int row = r / 18;
            int ck  = r - row * 18;
            int gh = h0 - RAD + row;
            int gw = w0 - RAD + ck * 4;
            dst = smbase + (unsigned)(ch * CHF + row * P2 + ck * 4) * 4u;
            if (gh < 0 || gh >= HH || gw < 0 || gw > WW - 4) {
                sz = 0; src = in2b;        // zero-fill chunk (re-zero every stage)
            } else {
                src = in2b + ((size_t)ch * HH + gh) * WW + gw;
            }
        } else {
            int r2 = r - IN2CK;
            int row = r2 >> 4;
            int ck  = r2 & 15;
            dst = smbase + (unsigned)(ch * CHF + IN2F + row * P1 + ck * 4) * 4u;
            src = in1b + ((size_t)ch * HH + (h0 + row)) * WW + (w0 + ck * 4);
        }
    };

    decode(tid, src0, dst0, sz0);
    if (has1) decode(tid + NT, src1, dst1, sz1);

    auto load_stage = [&]() {
        cp16(dst0, src0, sz0);
        src0 += CCH * HH * WW;
        dst0 += STAGE_B; if (dst0 >= smend) dst0 -= NSTAGE * STAGE_B;
        if (has1) {
            cp16(dst1, src1, sz1);
            src1 += CCH * HH * WW;
            dst1 += STAGE_B; if (dst1 >= smend) dst1 -= NSTAGE * STAGE_B;
        }
        asm volatile("cp.async.commit_group;\n");
    };

    // ---- accumulators: 9 dw x 4 px-pairs (8 px) ----
    unsigned long long acc[PATCH][4];
#pragma unroll
    for (int dw = 0; dw < PATCH; dw++)
#pragma unroll
        for (int j = 0; j < 4; j++) acc[dw][j] = 0ull;

    const int off_win = (hh + dh) * P2 + wgf * 8;      // window floats [0..15]
    const int off_a   = IN2F + hh * P1 + wgf * 8;      // in1 floats [0..7]

    load_stage();   // stage 0 -> group 0
    load_stage();   // stage 1 -> group 1

    const float* buf = sm;
    for (int s = 0; s < NSTEPS; s++) {
        asm volatile("cp.async.wait_group 1;\n");      // stage s resident
        __syncthreads();                                // publish + free buf (s-1)%3
        if (s + 2 < NSTEPS) load_stage();               // overwrite buf (s-1)%3
        else asm volatile("cp.async.commit_group;\n");  // keep group count moving

#pragma unroll
        for (int cc = 0; cc < CCH; cc++) {
            const float* chp = buf + cc * CHF;
            float4 q0 = *(const float4*)(chp + off_win);
            float4 q1 = *(const float4*)(chp + off_win + 4);
            float4 q2 = *(const float4*)(chp + off_win + 8);
            float4 q3 = *(const float4*)(chp + off_win + 12);
            float4 u0 = *(const float4*)(chp + off_a);
            float4 u1 = *(const float4*)(chp + off_a + 4);

            float f[16] = { q0.x,q0.y,q0.z,q0.w, q1.x,q1.y,q1.z,q1.w,
                            q2.x,q2.y,q2.z,q2.w, q3.x,q3.y,q3.z,q3.w };
            unsigned long long a2[4] = { pk(u0.x,u0.y), pk(u0.z,u0.w),
                                         pk(u1.x,u1.y), pk(u1.z,u1.w) };
            unsigned long long we[8];
#pragma unroll
            for (int k = 0; k < 8; k++) we[k] = pk(f[2*k], f[2*k+1]);   // aligned: free
            unsigned long long wo[7];
#pragma unroll
            for (int k = 0; k < 7; k++) wo[k] = pk(f[2*k+1], f[2*k+2]); // 2 MOV each

#pragma unroll
            for (int j = 0; j < 4; j++) {
#pragma unroll
                for (int e = 0; e < 5; e++) fma2(acc[2*e][j],   a2[j], we[j + e]);
#pragma unroll
                for (int o = 0; o < 4; o++) fma2(acc[2*o+1][j], a2[j], wo[j + o]);
            }
        }
        buf += STAGEF;
        if (buf >= sm + NSTAGE * STAGEF) buf = sm;
    }

    // ---- epilogue: 9 dw x 8 floats per thread ----
    const float scale = 1.0f / (float)CC_;
    float* outp = out + (((size_t)b * (PATCH*PATCH) + dh * PATCH) * HH + (h0 + hh)) * WW
                      + (w0 + wgf * 8);
#pragma unroll
    for (int dw = 0; dw < PATCH; dw++) {
        float v0, v1, v2, v3, v4, v5, v6, v7;
        upk(v0, v1, acc[dw][0]);
        upk(v2, v3, acc[dw][1]);
        upk(v4, v5, acc[dw][2]);
        upk(v6, v7, acc[dw][3]);
        float4 A = make_float4(v0*scale, v1*scale, v2*scale, v3*scale);
        float4 B = make_float4(v4*scale, v5*scale, v6*scale, v7*scale);
        float* p = outp + (size_t)dw * HH * WW;
        *(float4*)p       = A;
        *(float4*)(p + 4) = B;
    }
}

extern "C" void kernel_launch(void* const* d_in, const int* in_sizes, int n_in,
                              void* d_out, int out_size)
{
    const float* in1 = (const float*)d_in[0];
    const float* in2 = (const float*)d_in[1];
    float* out = (float*)d_out;

    dim3 grid(WW / TW, HH / TH, BB);   // 4 x 16 x 8 = 512 blocks
    dim3 block(NT);
    corr_kernel<<<grid, block>>>(in1, in2, out);
}

// round 4
// speedup vs baseline: 2.0584x; 2.0584x over previous
#include <cuda_runtime.h>
#include <cstdint>

// Spatial correlation sampler: out[b, dh*9+dw, h, w] =
//   (1/C) * sum_c in1[b,c,h,w] * in2[b,c,h+dh-4,w+dw-4]   (zero-padded)
// B=8, C=256, H=128, W=256, patch=9.
//
// R4 = R1 compute layout (proven fastest) + hoisted loader + ring-3 pipeline
// with a single barrier per stage.

#define BB   8
#define CC_  256
#define HH   128
#define WW   256
#define RAD  4
#define PATCH 9

#define TH   8
#define TW   32
#define CCH  4                        // channels per stage
#define NSTAGE 3                      // ring buffer depth
#define ROWS2 (TH + 2*RAD)            // 16 in2 rows
#define PITCH2 44                     // in2 row pitch (floats), 40 used
#define IN2F  (ROWS2 * PITCH2)        // 704 floats
#define CHF   (IN2F + TH * TW)        // 960 floats per channel
#define STAGEF (CCH * CHF)            // 3840 floats
#define STAGE_B (STAGEF * 4)          // 15360 bytes
#define IN2CK (ROWS2 * 11)            // 176 chunks per channel (in2)
#define CHCK  (IN2CK + TH * 8)        // 240 chunks per channel
#define TOTCK (CCH * CHCK)            // 960 chunks per stage
#define NT    576
#define NSTEPS (CC_ / CCH)            // 64 stages

__device__ __forceinline__ unsigned smem_u32(const void* p) {
    return (unsigned)__cvta_generic_to_shared(p);
}
__device__ __forceinline__ void cp16(unsigned dst, const void* src, int src_bytes) {
    asm volatile("cp.async.cg.shared.global [%0], [%1], 16, %2;\n"
                 :: "r"(dst), "l"(src), "r"(src_bytes));
}

__global__ void __launch_bounds__(NT, 1)
corr_kernel(const float* __restrict__ in1,
            const float* __restrict__ in2,
            float* __restrict__ out)
{
    __shared__ __align__(16) float sm[NSTAGE * STAGEF];   // 46080 B static

    const int tid = threadIdx.x;
    const int wg  = tid & 7;          // 8 w-groups x 4 px = 32 w
    const int hh  = (tid >> 3) & 7;   // row within tile
    const int dh  = tid >> 6;         // displacement row 0..8

    const int w0 = blockIdx.x * TW;
    const int h0 = blockIdx.y * TH;
    const int b  = blockIdx.z;

    const float* __restrict__ in1b = in1 + (size_t)b * CC_ * HH * WW;
    const float* __restrict__ in2b = in2 + (size_t)b * CC_ * HH * WW;

    // ---- hoisted loader slots (decoded once; per stage just advance) ----
    const unsigned smbase = smem_u32(sm);
    const unsigned smend  = smbase + NSTAGE * STAGE_B;

    const float* src0; unsigned dst0; int sz0;
    const float* src1 = in2b; unsigned dst1 = smbase; int sz1 = 0;
    const bool has1 = (tid < TOTCK - NT);   // tid < 384 owns a 2nd chunk

    auto decode = [&](int i, const float*& src, unsigned& dst, int& sz) {
        int ch = i / CHCK;                 // channel within stage 0..3
        int r  = i - ch * CHCK;
        sz = 16;
        if (r < IN2CK) {
            int row = r / 11;
            int ck  = r - row * 11;
            int gh = h0 - RAD + row;
            int gw = w0 - RAD + ck * 4;
            dst = smbase + (unsigned)(ch * CHF + row * PITCH2 + ck * 4) * 4u;
            if (gh < 0 || gh >= HH || gw < 0 || gw >= WW) {
                sz = 0; src = in2b;        // full-chunk zero fill each stage
            } else {
                src = in2b + ((size_t)ch * HH + gh) * WW + gw;
            }
        } else {
            int r2 = r - IN2CK;
            int row = r2 >> 3;
            int ck  = r2 & 7;
            dst = smbase + (unsigned)(ch * CHF + IN2F + row * TW + ck * 4) * 4u;
            src = in1b + ((size_t)ch * HH + (h0 + row)) * WW + (w0 + ck * 4);
        }
    };

    decode(tid, src0, dst0, sz0);
    if (has1) decode(tid + NT, src1, dst1, sz1);

    auto load_stage = [&]() {
        cp16(dst0, src0, sz0);
        src0 += CCH * HH * WW;
        dst0 += STAGE_B; if (dst0 >= smend) dst0 -= NSTAGE * STAGE_B;
        if (has1) {
            cp16(dst1, src1, sz1);
            src1 += CCH * HH * WW;
            dst1 += STAGE_B; if (dst1 >= smend) dst1 -= NSTAGE * STAGE_B;
        }
        asm volatile("cp.async.commit_group;\n");
    };

    // ---- accumulators ----
    float acc[PATCH][4];
#pragma unroll
    for (int dw = 0; dw < PATCH; dw++)
#pragma unroll
        for (int j = 0; j < 4; j++) acc[dw][j] = 0.0f;

    const int off_win = (hh + dh) * PITCH2 + wg * 4;     // in2 window start
    const int off_a   = IN2F + hh * TW + wg * 4;         // in1 pixels

    load_stage();   // stage 0
    load_stage();   // stage 1

    const float* buf = sm;
    for (int s = 0; s < NSTEPS; s++) {
        asm volatile("cp.async.wait_group 1;\n");        // stage s resident
        __syncthreads();                                  // publish s; frees slot (s-1)%3
        if (s + 2 < NSTEPS) load_stage();                 // -> slot (s-1)%3
        else asm volatile("cp.async.commit_group;\n");    // keep group accounting

#pragma unroll
        for (int cc = 0; cc < CCH; cc++) {
            const float* chp = buf + cc * CHF;
            const float4 a4 = *(const float4*)(chp + off_a);
            const float4* wp = (const float4*)(chp + off_win);
            float4 x0 = wp[0], x1 = wp[1], x2 = wp[2];
            float win[12] = { x0.x, x0.y, x0.z, x0.w,
                              x1.x, x1.y, x1.z, x1.w,
                              x2.x, x2.y, x2.z, x2.w };
            float a[4] = { a4.x, a4.y, a4.z, a4.w };
#pragma unroll
            for (int dw = 0; dw < PATCH; dw++)
#pragma unroll
                for (int j = 0; j < 4; j++)
                    acc[dw][j] = fmaf(a[j], win[j + dw], acc[dw][j]);
        }

        buf += STAGEF;
        if (buf >= sm + NSTAGE * STAGEF) buf = sm;
    }

    // ---- epilogue ----
    const float scale = 1.0f / (float)CC_;
    float* outp = out + (((size_t)b * (PATCH * PATCH) + dh * PATCH) * HH + (h0 + hh)) * WW
                      + (w0 + wg * 4);
#pragma unroll
    for (int dw = 0; dw < PATCH; dw++) {
        float4 v;
        v.x = acc[dw][0] * scale;
        v.y = acc[dw][1] * scale;
        v.z = acc[dw][2] * scale;
        v.w = acc[dw][3] * scale;
        *(float4*)(outp + (size_t)dw * HH * WW) = v;
    }
}

extern "C" void kernel_launch(void* const* d_in, const int* in_sizes, int n_in,
                              void* d_out, int out_size)
{
    const float* in1 = (const float*)d_in[0];
    const float* in2 = (const float*)d_in[1];
    float* out = (float*)d_out;

    dim3 grid(WW / TW, HH / TH, BB);   // 8 x 16 x 8 = 1024 blocks
    dim3 block(NT);
    corr_kernel<<<grid, block>>>(in1, in2, out);
}